// round 13
// baseline (speedup 1.0000x reference)
#include <cuda_runtime.h>
#include <cuda_bf16.h>
#include <cuda_fp16.h>
#include <cstdint>

#define BATCH 8
#define SEQ   2048
#define DIM   512
#define DK    64
#define ST    72            // smem row stride in halves (144 B, conflict-free ldmatrix)
#define ATILE (128 * ST)    // halves per 128-row x 64-col tile
#define QSCALE 0.180336884f // 0.125 * log2(e): softmax computed base-2, no max needed

// ---------------------------------------------------------------------------
// Scratch
// ---------------------------------------------------------------------------
__device__ __half g_Q[BATCH * SEQ * DK];
__device__ __half g_K[BATCH * SEQ * DK];
__device__ __half g_Wt[2 * DK * DIM];                 // W^T fp16: [which][n][k]
__device__ __half g_Xt[BATCH * DIM * SEQ];            // X^T fp16: [b][d][k]
__device__ __half g_P[(size_t)BATCH * SEQ * SEQ];     // UNNORMALIZED 2^s, fp16
__device__ float  g_Linv[BATCH * SEQ];                // 1 / rowsum

// ---------------------------------------------------------------------------
// Helpers
// ---------------------------------------------------------------------------
__device__ __forceinline__ uint32_t smem_u32(const void* p) {
    uint32_t a;
    asm("{ .reg .u64 t; cvta.to.shared.u64 t, %1; cvt.u32.u64 %0, t; }" : "=r"(a) : "l"(p));
    return a;
}
__device__ __forceinline__ uint32_t pack_ex2(float lo, float hi) {
    uint32_t r;
    asm("{ .reg .b32 t; cvt.rn.f16x2.f32 t, %2, %1; ex2.approx.f16x2 %0, t; }"
        : "=r"(r) : "f"(lo), "f"(hi));
    return r;
}
__device__ __forceinline__ uint32_t pack_h2(float lo, float hi) {
    uint32_t r;
    asm("cvt.rn.f16x2.f32 %0, %2, %1;" : "=r"(r) : "f"(lo), "f"(hi));
    return r;
}
__device__ __forceinline__ void ldsm4(uint32_t* r, uint32_t a) {
    asm volatile("ldmatrix.sync.aligned.m8n8.x4.shared.b16 {%0,%1,%2,%3}, [%4];"
        : "=r"(r[0]), "=r"(r[1]), "=r"(r[2]), "=r"(r[3]) : "r"(a));
}
__device__ __forceinline__ void ldsm2(uint32_t* r, uint32_t a) {
    asm volatile("ldmatrix.sync.aligned.m8n8.x2.shared.b16 {%0,%1}, [%2];"
        : "=r"(r[0]), "=r"(r[1]) : "r"(a));
}
__device__ __forceinline__ void mma_f16(float* d, const uint32_t* a, const uint32_t* b) {
    asm volatile(
        "mma.sync.aligned.m16n8k16.row.col.f32.f16.f16.f32 "
        "{%0,%1,%2,%3}, {%4,%5,%6,%7}, {%8,%9}, {%0,%1,%2,%3};"
        : "+f"(d[0]), "+f"(d[1]), "+f"(d[2]), "+f"(d[3])
        : "r"(a[0]), "r"(a[1]), "r"(a[2]), "r"(a[3]), "r"(b[0]), "r"(b[1]));
}

// 64x32 warp tile over one 16-wide k slab (attnP/proj path).
// B via 2x ldsm4, lane-mapped so reg pairs = (k-lo, k-hi) for nf, nf+1.
__device__ __forceinline__ void warp_mma_64x32(
    float acc[4][4][4], uint32_t sA, uint32_t sB,
    int wm, int wn, int lane, int k0)
{
    const int arow = lane & 15;
    const int acol = k0 + ((lane >> 4) << 3);
    const int brow = (lane & 7) + ((lane >> 4) << 3);
    const int bcol = k0 + ((lane >> 3) & 1) * 8;

    uint32_t a[4][4], bq[2][4];
#pragma unroll
    for (int mf = 0; mf < 4; mf++)
        ldsm4(a[mf], sA + (uint32_t)(((wm * 64 + mf * 16 + arow) * ST + acol) * 2));
#pragma unroll
    for (int pr = 0; pr < 2; pr++)
        ldsm4(bq[pr], sB + (uint32_t)(((wn * 32 + pr * 16 + brow) * ST + bcol) * 2));
#pragma unroll
    for (int mf = 0; mf < 4; mf++)
#pragma unroll
        for (int nf = 0; nf < 4; nf++)
            mma_f16(acc[mf][nf], a[mf], &bq[nf >> 1][(nf & 1) * 2]);
}

// 64x64 warp tile over one 16-wide k slab (px path): 32 MMAs, 128 B/MMA smem.
__device__ __forceinline__ void warp_mma_64x64(
    float acc[4][8][4], uint32_t sA, uint32_t sB,
    int wm, int wn, int lane, int k0)
{
    const int arow = lane & 15;
    const int acol = k0 + ((lane >> 4) << 3);
    const int brow = (lane & 7) + ((lane >> 4) << 3);
    const int bcol = k0 + ((lane >> 3) & 1) * 8;

    uint32_t a[4][4], bq[4][4];
#pragma unroll
    for (int mf = 0; mf < 4; mf++)
        ldsm4(a[mf], sA + (uint32_t)(((wm * 64 + mf * 16 + arow) * ST + acol) * 2));
#pragma unroll
    for (int pr = 0; pr < 4; pr++)
        ldsm4(bq[pr], sB + (uint32_t)(((wn * 64 + pr * 16 + brow) * ST + bcol) * 2));
#pragma unroll
    for (int mf = 0; mf < 4; mf++)
#pragma unroll
        for (int nf = 0; nf < 8; nf++)
            mma_f16(acc[mf][nf], a[mf], &bq[nf >> 1][(nf & 1) * 2]);
}

#define CP_ASYNC16(saddr, gptr) \
    asm volatile("cp.async.cg.shared.global [%0], [%1], 16;" :: "r"(saddr), "l"(gptr))
#define CP_COMMIT() asm volatile("cp.async.commit_group;" ::: "memory")
#define CP_WAIT1()  asm volatile("cp.async.wait_group 1;" ::: "memory")

#define ATTNP_SMEM (4 * ATILE * 2 + 2048)   // Q + 3 K stages + sL = 75776 B -> 2 CTAs/SM
#define PXSE       (256 * ST)               // px stage halves (P 128 + X 128 rows)
#define PX_SMEM    (3 * PXSE * 2)           // 110592 B -> 2 CTAs/SM
#define PROJ_SMEM  ((128 * ST + 64 * ST) * 2)  // A tile + Wt chunk = 27648 B

// ---------------------------------------------------------------------------
// prep: Wt[which][n][k] = fp16(W[k][n]) via conflict-free 32x33 transpose.
// ---------------------------------------------------------------------------
__global__ void prep_kernel(const float* __restrict__ WQ, const float* __restrict__ WK)
{
    __shared__ float t[32][33];
    const int which = blockIdx.y;
    const float* W = which ? WK : WQ;
    __half* Wt = g_Wt + which * (DK * DIM);
    const int k0 = blockIdx.x * 32;
    const int tx = threadIdx.x, ty = threadIdx.y;

    for (int d0 = 0; d0 < DK; d0 += 32) {
#pragma unroll
        for (int i = 0; i < 4; i++)
            t[ty + 8 * i][tx] = W[(long)(k0 + ty + 8 * i) * DK + d0 + tx];
        __syncthreads();
#pragma unroll
        for (int i = 0; i < 4; i++)
            Wt[(long)(d0 + ty + 8 * i) * DIM + k0 + tx] = __float2half_rn(t[tx][ty + 8 * i]);
        __syncthreads();
    }
}

// ---------------------------------------------------------------------------
// proj: grid (128, 2). y=0: Q = (h@WQ+bQ)*QSCALE; y=1: K = X@WK+bK -> fp16.
// ---------------------------------------------------------------------------
__global__ __launch_bounds__(256) void proj_kernel(
    const float* __restrict__ X, const float* __restrict__ h,
    const float* __restrict__ bQ, const float* __restrict__ bK)
{
    extern __shared__ __half psm[];
    __half* sA = psm;                 // [128][ST]
    __half* sW = psm + 128 * ST;      // [64][ST]

    const int tid = threadIdx.x;
    const int which = blockIdx.y;
    const float* A    = which ? X  : h;
    const float* bias = which ? bK : bQ;
    const float scale = which ? 1.0f : QSCALE;
    const __half* Wt  = g_Wt + which * (DK * DIM);
    __half* O = which ? g_K : g_Q;

    const int m0 = blockIdx.x * 128;
    const int w = tid >> 5, lane = tid & 31;
    const int ws = w >> 1, wn = w & 1;      // 4 x 2 warps, 32x32 tiles

    float acc[2][4][4];
#pragma unroll
    for (int mf = 0; mf < 2; mf++)
#pragma unroll
        for (int nf = 0; nf < 4; nf++)
#pragma unroll
            for (int r = 0; r < 4; r++) acc[mf][nf][r] = 0.0f;

    const uint32_t aA = smem_u32(sA);
    const uint32_t aW = smem_u32(sW);
    const int arow = lane & 15;
    const int asel = (lane >> 4) << 3;
    const int brow = lane & 7;
    const int bsel = ((lane >> 3) & 1) * 8;

    for (int kb = 0; kb < DIM; kb += 64) {
        __syncthreads();
#pragma unroll
        for (int i = tid; i < 128 * 16; i += 256) {
            int r = i >> 4, c4 = i & 15;
            float4 v = *(const float4*)(A + (long)(m0 + r) * DIM + kb + c4 * 4);
            *(uint2*)(sA + r * ST + c4 * 4) =
                make_uint2(pack_h2(v.x, v.y), pack_h2(v.z, v.w));
        }
#pragma unroll
        for (int i = tid; i < 64 * 8; i += 256) {
            int r = i >> 3, c = i & 7;
            *(uint4*)(sW + r * ST + c * 8) =
                *(const uint4*)(Wt + (long)r * DIM + kb + c * 8);
        }
        __syncthreads();

#pragma unroll
        for (int ks = 0; ks < 4; ks++) {
            const int k0 = ks * 16;
            uint32_t a[2][4], bb[4][2];
#pragma unroll
            for (int mf = 0; mf < 2; mf++)
                ldsm4(a[mf], aA + (uint32_t)(((ws * 32 + mf * 16 + arow) * ST + k0 + asel) * 2));
#pragma unroll
            for (int nf = 0; nf < 4; nf++)
                ldsm2(bb[nf], aW + (uint32_t)(((wn * 32 + nf * 8 + brow) * ST + k0 + bsel) * 2));
#pragma unroll
            for (int mf = 0; mf < 2; mf++)
#pragma unroll
                for (int nf = 0; nf < 4; nf++) mma_f16(acc[mf][nf], a[mf], bb[nf]);
        }
    }

    const int g = lane >> 2, tg = lane & 3;
#pragma unroll
    for (int mf = 0; mf < 2; mf++) {
        const int r0 = m0 + ws * 32 + mf * 16 + g;
#pragma unroll
        for (int nf = 0; nf < 4; nf++) {
            const int c = wn * 32 + nf * 8 + tg * 2;
            const float b0 = __ldg(bias + c), b1 = __ldg(bias + c + 1);
            *(uint32_t*)(O + (long)r0 * DK + c) =
                pack_h2((acc[mf][nf][0] + b0) * scale, (acc[mf][nf][1] + b1) * scale);
            *(uint32_t*)(O + (long)(r0 + 8) * DK + c) =
                pack_h2((acc[mf][nf][2] + b0) * scale, (acc[mf][nf][3] + b1) * scale);
        }
    }
}

// ---------------------------------------------------------------------------
// attnP: grid (16, 8, 2).
//   z=0: S = Q K^T (base-2), P~ = 2^S fp16 unnormalized, store 1/rowsum.
//   z=1: splitX — Xt[b][d][k] = fp16(X[b][k][d])
// ---------------------------------------------------------------------------
__device__ __forceinline__ void attnp_issue_k(
    __half* sK, const __half* gK, int jt, int tid)
{
    __half* st = sK + (jt % 3) * ATILE;
    const __half* g = gK + (size_t)jt * 128 * DK;
#pragma unroll
    for (int i = tid; i < 1024; i += 256) {
        int r = i >> 3, c = i & 7;
        CP_ASYNC16(smem_u32(st + r * ST + c * 8), g + r * DK + c * 8);
    }
}

__global__ __launch_bounds__(256, 2) void attnP_kernel(const float* __restrict__ X)
{
    extern __shared__ char smraw[];
    const int tid = threadIdx.x;

    if (blockIdx.z == 1) {
        float* t = (float*)smraw;   // [32][33]
        const int b  = blockIdx.y;
        const int d0 = blockIdx.x * 32;
        const int tx = tid & 31, ty = tid >> 5;
        for (int k0 = 0; k0 < SEQ; k0 += 32) {
#pragma unroll
            for (int i = 0; i < 4; i++)
                t[(ty + 8 * i) * 33 + tx] =
                    X[((long)b * SEQ + k0 + ty + 8 * i) * DIM + d0 + tx];
            __syncthreads();
#pragma unroll
            for (int i = 0; i < 4; i++)
                g_Xt[((long)b * DIM + d0 + ty + 8 * i) * SEQ + k0 + tx] =
                    __float2half_rn(t[tx * 33 + ty + 8 * i]);
            __syncthreads();
        }
        return;
    }

    __half* sQ = (__half*)smraw;
    __half* sK = sQ + ATILE;
    float*  sL = (float*)(smraw + 4 * ATILE * 2);   // [128][4]

    const int w = tid >> 5, lane = tid & 31;
    const int wm = w >> 2, wn = w & 3, g = lane >> 2, tg = lane & 3;
    const int m0 = blockIdx.x * 128, b = blockIdx.y;
    const __half* gQ = g_Q + ((size_t)b * SEQ + m0) * DK;
    const __half* gK = g_K + (size_t)b * SEQ * DK;

#pragma unroll
    for (int i = tid; i < 1024; i += 256) {
        int r = i >> 3, c = i & 7;
        *(uint4*)(sQ + r * ST + c * 8) = *(const uint4*)(gQ + r * DK + c * 8);
    }

    const uint32_t aQ = smem_u32(sQ);
    const uint32_t aK0 = smem_u32(sK);

    float lsum[8];
#pragma unroll
    for (int i = 0; i < 8; i++) lsum[i] = 0.0f;

    attnp_issue_k(sK, gK, 0, tid); CP_COMMIT();
    attnp_issue_k(sK, gK, 1, tid); CP_COMMIT();

    __half* Pb = g_P + ((size_t)b * SEQ + m0) * SEQ;

    for (int jt = 0; jt < 16; jt++) {
        CP_WAIT1();
        __syncthreads();
        if (jt + 2 < 16) attnp_issue_k(sK, gK, jt + 2, tid);
        CP_COMMIT();

        float acc[4][4][4];
#pragma unroll
        for (int mf = 0; mf < 4; mf++)
#pragma unroll
            for (int nf = 0; nf < 4; nf++)
#pragma unroll
                for (int r = 0; r < 4; r++) acc[mf][nf][r] = 0.0f;

        uint32_t aK = aK0 + (uint32_t)((jt % 3) * ATILE * 2);
#pragma unroll
        for (int ks = 0; ks < 4; ks++)
            warp_mma_64x32(acc, aQ, aK, wm, wn, lane, ks * 16);

        __half* Pt = Pb + (size_t)jt * 128;
#pragma unroll
        for (int mf = 0; mf < 4; mf++) {
            const int r0 = wm * 64 + mf * 16 + g;
#pragma unroll
            for (int hh = 0; hh < 2; hh++) {
                const int row = r0 + 8 * hh;
                __half2 hs = __floats2half2_rn(0.0f, 0.0f);
#pragma unroll
                for (int nf = 0; nf < 4; nf++) {
                    uint32_t pk = pack_ex2(acc[mf][nf][2 * hh], acc[mf][nf][2 * hh + 1]);
                    *(uint32_t*)(Pt + (size_t)row * SEQ + wn * 32 + nf * 8 + tg * 2) = pk;
                    hs = __hadd2(hs, *(__half2*)&pk);
                }
                float2 f2 = __half22float2(hs);
                lsum[mf * 2 + hh] += f2.x + f2.y;
            }
        }
    }

#pragma unroll
    for (int idx = 0; idx < 8; idx++) {
        lsum[idx] += __shfl_xor_sync(0xFFFFFFFFu, lsum[idx], 1);
        lsum[idx] += __shfl_xor_sync(0xFFFFFFFFu, lsum[idx], 2);
    }
    if (tg == 0) {
#pragma unroll
        for (int idx = 0; idx < 8; idx++) {
            int row = wm * 64 + (idx >> 1) * 16 + g + (idx & 1) * 8;
            sL[row * 4 + wn] = lsum[idx];
        }
    }
    __syncthreads();
    if (tid < 128) {
        float l = sL[tid * 4] + sL[tid * 4 + 1] + sL[tid * 4 + 2] + sL[tid * 4 + 3];
        g_Linv[(size_t)b * SEQ + m0 + tid] = 1.0f / l;
    }
}

// ---------------------------------------------------------------------------
// px: out[128q x 128d] = (P~ @ X^T) * Linv[row]
// 128 thr, 4 warps 2x2, warp tile 64x64 (128 B/MMA smem traffic),
// 3-stage ring, 2 CTAs/SM (two independent barrier domains).
// ---------------------------------------------------------------------------
__device__ __forceinline__ void px_issue(
    __half* smh, const __half* gP, const __half* gX, int kt, int tid)
{
    __half* st = smh + (kt % 3) * PXSE;
    const long ko = (long)kt * 64;
#pragma unroll
    for (int i = tid; i < 1024; i += 128) {     // P: 128 rows
        int r = i >> 3, c = i & 7;
        CP_ASYNC16(smem_u32(st + r * ST + c * 8), gP + (long)r * SEQ + ko + c * 8);
    }
    __half* sx = st + 128 * ST;
#pragma unroll
    for (int i = tid; i < 1024; i += 128) {     // X: 128 rows
        int r = i >> 3, c = i & 7;
        CP_ASYNC16(smem_u32(sx + r * ST + c * 8), gX + (long)r * SEQ + ko + c * 8);
    }
}

__global__ __launch_bounds__(128, 2) void px_kernel(float* __restrict__ out)
{
    extern __shared__ __half smh[];

    const int tid = threadIdx.x, w = tid >> 5, lane = tid & 31;
    const int wm = w >> 1, wn = w & 1;
    const int m0 = blockIdx.x * 128, n0 = blockIdx.y * 128, b = blockIdx.z;

    const __half* gP = g_P  + ((size_t)b * SEQ + m0) * SEQ;
    const __half* gX = g_Xt + ((size_t)b * DIM + n0) * SEQ;

    float acc[4][8][4];
#pragma unroll
    for (int mf = 0; mf < 4; mf++)
#pragma unroll
        for (int nf = 0; nf < 8; nf++)
#pragma unroll
            for (int r = 0; r < 4; r++) acc[mf][nf][r] = 0.0f;

    px_issue(smh, gP, gX, 0, tid); CP_COMMIT();
    px_issue(smh, gP, gX, 1, tid); CP_COMMIT();

    const uint32_t base0 = smem_u32(smh);
    for (int kt = 0; kt < SEQ / 64; kt++) {
        CP_WAIT1();
        __syncthreads();
        if (kt + 2 < SEQ / 64) px_issue(smh, gP, gX, kt + 2, tid);
        CP_COMMIT();

        uint32_t aP = base0 + (uint32_t)((kt % 3) * PXSE * 2);
        uint32_t aX = aP + 128 * ST * 2;
#pragma unroll
        for (int ks = 0; ks < 4; ks++)
            warp_mma_64x64(acc, aP, aX, wm, wn, lane, ks * 16);
    }

    const int g = lane >> 2, tg = lane & 3;
    float* dst = out + ((size_t)b * SEQ + m0) * DIM + n0;
    const float* Li = g_Linv + (size_t)b * SEQ + m0;
#pragma unroll
    for (int mf = 0; mf < 4; mf++) {
        int r0 = wm * 64 + mf * 16 + g;
        float i0 = Li[r0];
        float i1 = Li[r0 + 8];
#pragma unroll
        for (int nf = 0; nf < 8; nf++) {
            int c = wn * 64 + nf * 8 + tg * 2;
            *(float2*)&dst[(size_t)r0 * DIM + c] =
                make_float2(acc[mf][nf][0] * i0, acc[mf][nf][1] * i0);
            *(float2*)&dst[(size_t)(r0 + 8) * DIM + c] =
                make_float2(acc[mf][nf][2] * i1, acc[mf][nf][3] * i1);
        }
    }
}

// ---------------------------------------------------------------------------
// kernel_launch
// ---------------------------------------------------------------------------
extern "C" void kernel_launch(void* const* d_in, const int* in_sizes, int n_in,
                              void* d_out, int out_size)
{
    const float* X  = (const float*)d_in[0];
    const float* h  = (const float*)d_in[1];
    const float* WQ = (const float*)d_in[2];
    const float* bQ = (const float*)d_in[3];
    const float* WK = (const float*)d_in[4];
    const float* bK = (const float*)d_in[5];
    float* out = (float*)d_out;

    static int cfg = 0;
    if (!cfg) {
        cudaFuncSetAttribute(proj_kernel,  cudaFuncAttributeMaxDynamicSharedMemorySize, PROJ_SMEM);
        cudaFuncSetAttribute(attnP_kernel, cudaFuncAttributeMaxDynamicSharedMemorySize, ATTNP_SMEM);
        cudaFuncSetAttribute(px_kernel,    cudaFuncAttributeMaxDynamicSharedMemorySize, PX_SMEM);
        cfg = 1;
    }

    prep_kernel<<<dim3(16, 2), dim3(32, 8)>>>(WQ, WK);
    proj_kernel<<<dim3(128, 2), 256, PROJ_SMEM>>>(X, h, bQ, bK);
    attnP_kernel<<<dim3(16, 8, 2), 256, ATTNP_SMEM>>>(X);
    px_kernel<<<dim3(SEQ / 128, DIM / 128, BATCH), 128, PX_SMEM>>>(out);
}

// round 14
// speedup vs baseline: 1.0106x; 1.0106x over previous
#include <cuda_runtime.h>
#include <cuda_bf16.h>
#include <cuda_fp16.h>
#include <cstdint>

#define BATCH 8
#define SEQ   2048
#define DIM   512
#define DK    64
#define ST    72            // smem row stride in halves (144 B, conflict-free ldmatrix)
#define ST2   136           // X-tile row stride in halves (272 B, conflict-free ldsm.trans)
#define ATILE (128 * ST)    // halves per 128-row x 64-col tile
#define QSCALE 0.180336884f // 0.125 * log2(e): softmax computed base-2, no max needed

// ---------------------------------------------------------------------------
// Scratch
// ---------------------------------------------------------------------------
__device__ __half g_Q[BATCH * SEQ * DK];
__device__ __half g_K[BATCH * SEQ * DK];
__device__ __half g_Xh[(size_t)BATCH * SEQ * DIM];    // X fp16, natural [b][k][d]
__device__ __half g_P[(size_t)BATCH * SEQ * SEQ];     // UNNORMALIZED 2^s, fp16
__device__ float  g_Linv[BATCH * SEQ];                // 1 / rowsum

// ---------------------------------------------------------------------------
// Helpers
// ---------------------------------------------------------------------------
__device__ __forceinline__ uint32_t smem_u32(const void* p) {
    uint32_t a;
    asm("{ .reg .u64 t; cvta.to.shared.u64 t, %1; cvt.u32.u64 %0, t; }" : "=r"(a) : "l"(p));
    return a;
}
__device__ __forceinline__ uint32_t pack_ex2(float lo, float hi) {
    uint32_t r;
    asm("{ .reg .b32 t; cvt.rn.f16x2.f32 t, %2, %1; ex2.approx.f16x2 %0, t; }"
        : "=r"(r) : "f"(lo), "f"(hi));
    return r;
}
__device__ __forceinline__ uint32_t pack_h2(float lo, float hi) {
    uint32_t r;
    asm("cvt.rn.f16x2.f32 %0, %2, %1;" : "=r"(r) : "f"(lo), "f"(hi));
    return r;
}
__device__ __forceinline__ void ldsm4(uint32_t* r, uint32_t a) {
    asm volatile("ldmatrix.sync.aligned.m8n8.x4.shared.b16 {%0,%1,%2,%3}, [%4];"
        : "=r"(r[0]), "=r"(r[1]), "=r"(r[2]), "=r"(r[3]) : "r"(a));
}
__device__ __forceinline__ void ldsm4t(uint32_t* r, uint32_t a) {
    asm volatile("ldmatrix.sync.aligned.m8n8.x4.trans.shared.b16 {%0,%1,%2,%3}, [%4];"
        : "=r"(r[0]), "=r"(r[1]), "=r"(r[2]), "=r"(r[3]) : "r"(a));
}
__device__ __forceinline__ void mma_f16(float* d, const uint32_t* a, const uint32_t* b) {
    asm volatile(
        "mma.sync.aligned.m16n8k16.row.col.f32.f16.f16.f32 "
        "{%0,%1,%2,%3}, {%4,%5,%6,%7}, {%8,%9}, {%0,%1,%2,%3};"
        : "+f"(d[0]), "+f"(d[1]), "+f"(d[2]), "+f"(d[3])
        : "r"(a[0]), "r"(a[1]), "r"(a[2]), "r"(a[3]), "r"(b[0]), "r"(b[1]));
}

// 64x32 warp tile, B stored [n][k] row-major (non-trans path; attnP).
__device__ __forceinline__ void warp_mma_64x32(
    float acc[4][4][4], uint32_t sA, uint32_t sB,
    int wm, int wn, int lane, int k0)
{
    const int arow = lane & 15;
    const int acol = k0 + ((lane >> 4) << 3);
    const int brow = (lane & 7) + ((lane >> 4) << 3);
    const int bcol = k0 + ((lane >> 3) & 1) * 8;

    uint32_t a[4][4], bq[2][4];
#pragma unroll
    for (int mf = 0; mf < 4; mf++)
        ldsm4(a[mf], sA + (uint32_t)(((wm * 64 + mf * 16 + arow) * ST + acol) * 2));
#pragma unroll
    for (int pr = 0; pr < 2; pr++)
        ldsm4(bq[pr], sB + (uint32_t)(((wn * 32 + pr * 16 + brow) * ST + bcol) * 2));
#pragma unroll
    for (int mf = 0; mf < 4; mf++)
#pragma unroll
        for (int nf = 0; nf < 4; nf++)
            mma_f16(acc[mf][nf], a[mf], &bq[nf >> 1][(nf & 1) * 2]);
}

// 64x32 warp tile, B stored [k][n] row-major (ldsm4.trans path; px).
// Tile order within one ldsm4t (t = lane>>3): t0=(k-lo,n-oct0) t1=(k-hi,oct0)
// t2=(k-lo,oct1) t3=(k-hi,oct1) -> regs (0,1)/(2,3) = b-frag pairs per octet.
__device__ __forceinline__ void warp_mma_64x32_bt(
    float acc[4][4][4], uint32_t sA, uint32_t sB, uint32_t bstride /*halves*/,
    int wm, int wn, int lane, int k0)
{
    const int arow = lane & 15;
    const int acol = k0 + ((lane >> 4) << 3);
    const int bkrow = k0 + ((lane >> 3) & 1) * 8 + (lane & 7);
    const int bncol = wn * 32 + (lane >> 4) * 8;

    uint32_t a[4][4], bq[2][4];
#pragma unroll
    for (int mf = 0; mf < 4; mf++)
        ldsm4(a[mf], sA + (uint32_t)(((wm * 64 + mf * 16 + arow) * ST + acol) * 2));
#pragma unroll
    for (int pr = 0; pr < 2; pr++)
        ldsm4t(bq[pr], sB + (uint32_t)((bkrow * bstride + bncol + pr * 16) * 2));
#pragma unroll
    for (int mf = 0; mf < 4; mf++)
#pragma unroll
        for (int nf = 0; nf < 4; nf++)
            mma_f16(acc[mf][nf], a[mf], &bq[nf >> 1][(nf & 1) * 2]);
}

#define CP_ASYNC16(saddr, gptr) \
    asm volatile("cp.async.cg.shared.global [%0], [%1], 16;" :: "r"(saddr), "l"(gptr))
#define CP_COMMIT() asm volatile("cp.async.commit_group;" ::: "memory")
#define CP_WAIT1()  asm volatile("cp.async.wait_group 1;" ::: "memory")

#define ATTNP_SMEM (4 * ATILE * 2 + 2048)        // 75776 B -> 2 CTAs/SM
#define PXSE       (128 * ST + 64 * ST2)          // px stage halves: P[128][ST] + X[64][ST2]
#define PX_SMEM    (3 * PXSE * 2)                 // 107520 B -> 2 CTAs/SM
#define PROJ_SMEM  ((128 * ST + 64 * ST) * 2)     // A tile + W chunk = 27648 B

// ---------------------------------------------------------------------------
// proj: grid (128, 2). y=0: Q = (h@WQ+bQ)*QSCALE; y=1: K = X@WK+bK -> fp16.
// W loaded [k][n] (no transpose, no prep kernel); B frags via ldsm4.trans.
// K-role write-through: fp16 X tiles also stored to g_Xh (natural layout).
// ---------------------------------------------------------------------------
__global__ __launch_bounds__(256) void proj_kernel(
    const float* __restrict__ X, const float* __restrict__ h,
    const float* __restrict__ WQ, const float* __restrict__ bQ,
    const float* __restrict__ WK, const float* __restrict__ bK)
{
    extern __shared__ __half psm[];
    __half* sA = psm;                 // [128][ST]  (rows = m, cols = k-chunk)
    __half* sW = psm + 128 * ST;      // [64][ST]   (rows = k-chunk, cols = n)

    const int tid = threadIdx.x;
    const int which = blockIdx.y;
    const float* A    = which ? X  : h;
    const float* W    = which ? WK : WQ;
    const float* bias = which ? bK : bQ;
    const float scale = which ? 1.0f : QSCALE;
    __half* O = which ? g_K : g_Q;

    const int m0 = blockIdx.x * 128;
    const int w = tid >> 5, lane = tid & 31;
    const int ws = w >> 1, wn = w & 1;      // 4 x 2 warps, 32x32 tiles

    float acc[2][4][4];
#pragma unroll
    for (int mf = 0; mf < 2; mf++)
#pragma unroll
        for (int nf = 0; nf < 4; nf++)
#pragma unroll
            for (int r = 0; r < 4; r++) acc[mf][nf][r] = 0.0f;

    const uint32_t aA = smem_u32(sA);
    const uint32_t aW = smem_u32(sW);
    const int arow = lane & 15;
    const int asel = (lane >> 4) << 3;
    const int bkrow = ((lane >> 3) & 1) * 8 + (lane & 7);
    const int bncol = wn * 32 + (lane >> 4) * 8;

    for (int kb = 0; kb < DIM; kb += 64) {
        __syncthreads();
        // A tile: 128 rows x 64 cols fp32 -> fp16 (+ write-through to g_Xh for K role)
#pragma unroll
        for (int i = tid; i < 128 * 16; i += 256) {
            int r = i >> 4, c4 = i & 15;
            float4 v = *(const float4*)(A + (long)(m0 + r) * DIM + kb + c4 * 4);
            uint2 pk = make_uint2(pack_h2(v.x, v.y), pack_h2(v.z, v.w));
            *(uint2*)(sA + r * ST + c4 * 4) = pk;
            if (which)
                *(uint2*)(g_Xh + (size_t)(m0 + r) * DIM + kb + c4 * 4) = pk;
        }
        // W chunk: 64 k-rows x 64 n fp32 -> fp16 (natural layout, coalesced)
#pragma unroll
        for (int i = tid; i < 64 * 16; i += 256) {
            int r = i >> 4, c4 = i & 15;
            float4 v = *(const float4*)(W + (long)(kb + r) * DK + c4 * 4);
            *(uint2*)(sW + r * ST + c4 * 4) =
                make_uint2(pack_h2(v.x, v.y), pack_h2(v.z, v.w));
        }
        __syncthreads();

#pragma unroll
        for (int ks = 0; ks < 4; ks++) {
            const int k0 = ks * 16;
            uint32_t a[2][4], bq[2][4];
#pragma unroll
            for (int mf = 0; mf < 2; mf++)
                ldsm4(a[mf], aA + (uint32_t)(((ws * 32 + mf * 16 + arow) * ST + k0 + asel) * 2));
#pragma unroll
            for (int pr = 0; pr < 2; pr++)
                ldsm4t(bq[pr], aW + (uint32_t)(((k0 + bkrow) * ST + bncol + pr * 16) * 2));
#pragma unroll
            for (int mf = 0; mf < 2; mf++)
#pragma unroll
                for (int nf = 0; nf < 4; nf++)
                    mma_f16(acc[mf][nf], a[mf], &bq[nf >> 1][(nf & 1) * 2]);
        }
    }

    const int g = lane >> 2, tg = lane & 3;
#pragma unroll
    for (int mf = 0; mf < 2; mf++) {
        const int r0 = m0 + ws * 32 + mf * 16 + g;
#pragma unroll
        for (int nf = 0; nf < 4; nf++) {
            const int c = wn * 32 + nf * 8 + tg * 2;
            const float b0 = __ldg(bias + c), b1 = __ldg(bias + c + 1);
            *(uint32_t*)(O + (long)r0 * DK + c) =
                pack_h2((acc[mf][nf][0] + b0) * scale, (acc[mf][nf][1] + b1) * scale);
            *(uint32_t*)(O + (long)(r0 + 8) * DK + c) =
                pack_h2((acc[mf][nf][2] + b0) * scale, (acc[mf][nf][3] + b1) * scale);
        }
    }
}

// ---------------------------------------------------------------------------
// attnP: grid (16, 8). S = Q K^T (base-2), P~ = 2^S fp16, store 1/rowsum.
// ---------------------------------------------------------------------------
__device__ __forceinline__ void attnp_issue_k(
    __half* sK, const __half* gK, int jt, int tid)
{
    __half* st = sK + (jt % 3) * ATILE;
    const __half* g = gK + (size_t)jt * 128 * DK;
#pragma unroll
    for (int i = tid; i < 1024; i += 256) {
        int r = i >> 3, c = i & 7;
        CP_ASYNC16(smem_u32(st + r * ST + c * 8), g + r * DK + c * 8);
    }
}

__global__ __launch_bounds__(256, 2) void attnP_kernel()
{
    extern __shared__ char smraw[];
    __half* sQ = (__half*)smraw;
    __half* sK = sQ + ATILE;
    float*  sL = (float*)(smraw + 4 * ATILE * 2);   // [128][4]

    const int tid = threadIdx.x;
    const int w = tid >> 5, lane = tid & 31;
    const int wm = w >> 2, wn = w & 3, g = lane >> 2, tg = lane & 3;
    const int m0 = blockIdx.x * 128, b = blockIdx.y;
    const __half* gQ = g_Q + ((size_t)b * SEQ + m0) * DK;
    const __half* gK = g_K + (size_t)b * SEQ * DK;

#pragma unroll
    for (int i = tid; i < 1024; i += 256) {
        int r = i >> 3, c = i & 7;
        *(uint4*)(sQ + r * ST + c * 8) = *(const uint4*)(gQ + r * DK + c * 8);
    }

    const uint32_t aQ = smem_u32(sQ);
    const uint32_t aK0 = smem_u32(sK);

    float lsum[8];
#pragma unroll
    for (int i = 0; i < 8; i++) lsum[i] = 0.0f;

    attnp_issue_k(sK, gK, 0, tid); CP_COMMIT();
    attnp_issue_k(sK, gK, 1, tid); CP_COMMIT();

    __half* Pb = g_P + ((size_t)b * SEQ + m0) * SEQ;

    for (int jt = 0; jt < 16; jt++) {
        CP_WAIT1();
        __syncthreads();
        if (jt + 2 < 16) attnp_issue_k(sK, gK, jt + 2, tid);
        CP_COMMIT();

        float acc[4][4][4];
#pragma unroll
        for (int mf = 0; mf < 4; mf++)
#pragma unroll
            for (int nf = 0; nf < 4; nf++)
#pragma unroll
                for (int r = 0; r < 4; r++) acc[mf][nf][r] = 0.0f;

        uint32_t aK = aK0 + (uint32_t)((jt % 3) * ATILE * 2);
#pragma unroll
        for (int ks = 0; ks < 4; ks++)
            warp_mma_64x32(acc, aQ, aK, wm, wn, lane, ks * 16);

        __half* Pt = Pb + (size_t)jt * 128;
#pragma unroll
        for (int mf = 0; mf < 4; mf++) {
            const int r0 = wm * 64 + mf * 16 + g;
#pragma unroll
            for (int hh = 0; hh < 2; hh++) {
                const int row = r0 + 8 * hh;
                __half2 hs = __floats2half2_rn(0.0f, 0.0f);
#pragma unroll
                for (int nf = 0; nf < 4; nf++) {
                    uint32_t pk = pack_ex2(acc[mf][nf][2 * hh], acc[mf][nf][2 * hh + 1]);
                    *(uint32_t*)(Pt + (size_t)row * SEQ + wn * 32 + nf * 8 + tg * 2) = pk;
                    hs = __hadd2(hs, *(__half2*)&pk);
                }
                float2 f2 = __half22float2(hs);
                lsum[mf * 2 + hh] += f2.x + f2.y;
            }
        }
    }

#pragma unroll
    for (int idx = 0; idx < 8; idx++) {
        lsum[idx] += __shfl_xor_sync(0xFFFFFFFFu, lsum[idx], 1);
        lsum[idx] += __shfl_xor_sync(0xFFFFFFFFu, lsum[idx], 2);
    }
    if (tg == 0) {
#pragma unroll
        for (int idx = 0; idx < 8; idx++) {
            int row = wm * 64 + (idx >> 1) * 16 + g + (idx & 1) * 8;
            sL[row * 4 + wn] = lsum[idx];
        }
    }
    __syncthreads();
    if (tid < 128) {
        float l = sL[tid * 4] + sL[tid * 4 + 1] + sL[tid * 4 + 2] + sL[tid * 4 + 3];
        g_Linv[(size_t)b * SEQ + m0 + tid] = 1.0f / l;
    }
}

// ---------------------------------------------------------------------------
// px: out[128q x 128d] = (P~ @ X) * Linv[row]
// X tiles in natural [k][d] layout (g_Xh); B frags via ldsm4.trans.
// 256 thr, 8 warps 2x4 (64x32 tiles), 3-stage ring, 2 CTAs/SM.
// ---------------------------------------------------------------------------
__device__ __forceinline__ void px_issue(
    __half* smh, const __half* gP, const __half* gX, int kt, int tid)
{
    __half* st = smh + (kt % 3) * PXSE;
    const long ko = (long)kt * 64;
#pragma unroll
    for (int i = tid; i < 1024; i += 256) {     // P: 128 q-rows x 64 k
        int r = i >> 3, c = i & 7;
        CP_ASYNC16(smem_u32(st + r * ST + c * 8), gP + (long)r * SEQ + ko + c * 8);
    }
    __half* sx = st + 128 * ST;                 // X: 64 k-rows x 128 d
#pragma unroll
    for (int i = tid; i < 1024; i += 256) {
        int r = i >> 4, c = i & 15;
        CP_ASYNC16(smem_u32(sx + r * ST2 + c * 8), gX + (ko + r) * DIM + c * 8);
    }
}

__global__ __launch_bounds__(256, 2) void px_kernel(float* __restrict__ out)
{
    extern __shared__ __half smh[];

    const int tid = threadIdx.x, w = tid >> 5, lane = tid & 31;
    const int wm = w >> 2, wn = w & 3;
    const int m0 = blockIdx.x * 128, n0 = blockIdx.y * 128, b = blockIdx.z;

    const __half* gP = g_P  + ((size_t)b * SEQ + m0) * SEQ;
    const __half* gX = g_Xh + (size_t)b * SEQ * DIM + n0;

    float acc[4][4][4];
#pragma unroll
    for (int mf = 0; mf < 4; mf++)
#pragma unroll
        for (int nf = 0; nf < 4; nf++)
#pragma unroll
            for (int r = 0; r < 4; r++) acc[mf][nf][r] = 0.0f;

    px_issue(smh, gP, gX, 0, tid); CP_COMMIT();
    px_issue(smh, gP, gX, 1, tid); CP_COMMIT();

    const uint32_t base0 = smem_u32(smh);
    for (int kt = 0; kt < SEQ / 64; kt++) {
        CP_WAIT1();
        __syncthreads();
        if (kt + 2 < SEQ / 64) px_issue(smh, gP, gX, kt + 2, tid);
        CP_COMMIT();

        uint32_t aP = base0 + (uint32_t)((kt % 3) * PXSE * 2);
        uint32_t aX = aP + 128 * ST * 2;
#pragma unroll
        for (int ks = 0; ks < 4; ks++)
            warp_mma_64x32_bt(acc, aP, aX, ST2, wm, wn, lane, ks * 16);
    }

    const int g = lane >> 2, tg = lane & 3;
    float* dst = out + ((size_t)b * SEQ + m0) * DIM + n0;
    const float* Li = g_Linv + (size_t)b * SEQ + m0;
#pragma unroll
    for (int mf = 0; mf < 4; mf++) {
        int r0 = wm * 64 + mf * 16 + g;
        float i0 = Li[r0];
        float i1 = Li[r0 + 8];
#pragma unroll
        for (int nf = 0; nf < 4; nf++) {
            int c = wn * 32 + nf * 8 + tg * 2;
            *(float2*)&dst[(size_t)r0 * DIM + c] =
                make_float2(acc[mf][nf][0] * i0, acc[mf][nf][1] * i0);
            *(float2*)&dst[(size_t)(r0 + 8) * DIM + c] =
                make_float2(acc[mf][nf][2] * i1, acc[mf][nf][3] * i1);
        }
    }
}

// ---------------------------------------------------------------------------
// kernel_launch
// ---------------------------------------------------------------------------
extern "C" void kernel_launch(void* const* d_in, const int* in_sizes, int n_in,
                              void* d_out, int out_size)
{
    const float* X  = (const float*)d_in[0];
    const float* h  = (const float*)d_in[1];
    const float* WQ = (const float*)d_in[2];
    const float* bQ = (const float*)d_in[3];
    const float* WK = (const float*)d_in[4];
    const float* bK = (const float*)d_in[5];
    float* out = (float*)d_out;

    static int cfg = 0;
    if (!cfg) {
        cudaFuncSetAttribute(proj_kernel,  cudaFuncAttributeMaxDynamicSharedMemorySize, PROJ_SMEM);
        cudaFuncSetAttribute(attnP_kernel, cudaFuncAttributeMaxDynamicSharedMemorySize, ATTNP_SMEM);
        cudaFuncSetAttribute(px_kernel,    cudaFuncAttributeMaxDynamicSharedMemorySize, PX_SMEM);
        cfg = 1;
    }

    proj_kernel<<<dim3(128, 2), 256, PROJ_SMEM>>>(X, h, WQ, bQ, WK, bK);
    attnP_kernel<<<dim3(16, 8), 256, ATTNP_SMEM>>>();
    px_kernel<<<dim3(SEQ / 128, DIM / 128, BATCH), 256, PX_SMEM>>>(out);
}

// round 15
// speedup vs baseline: 1.0874x; 1.0759x over previous
#include <cuda_runtime.h>
#include <cuda_bf16.h>
#include <cuda_fp16.h>
#include <cstdint>

#define BATCH 8
#define SEQ   2048
#define DIM   512
#define DK    64
#define ST    72            // smem row stride in halves (144 B, conflict-free ldmatrix)
#define ST2   136           // X-tile row stride in halves (272 B, conflict-free ldsm.trans)
#define ATILE (128 * ST)    // halves per 128-row x 64-col tile
#define QSCALE 0.180336884f // 0.125 * log2(e): softmax computed base-2, no max needed

// ---------------------------------------------------------------------------
// Scratch
// ---------------------------------------------------------------------------
__device__ __half g_Q[BATCH * SEQ * DK];
__device__ __half g_K[BATCH * SEQ * DK];
__device__ __half g_Xh[(size_t)BATCH * SEQ * DIM];    // X fp16, natural [b][k][d]
__device__ __half g_P[(size_t)BATCH * SEQ * SEQ];     // UNNORMALIZED 2^s, fp16
__device__ float  g_Linv[BATCH * SEQ];                // 1 / rowsum

// ---------------------------------------------------------------------------
// Helpers
// ---------------------------------------------------------------------------
__device__ __forceinline__ uint32_t smem_u32(const void* p) {
    uint32_t a;
    asm("{ .reg .u64 t; cvta.to.shared.u64 t, %1; cvt.u32.u64 %0, t; }" : "=r"(a) : "l"(p));
    return a;
}
__device__ __forceinline__ uint32_t pack_ex2(float lo, float hi) {
    uint32_t r;
    asm("{ .reg .b32 t; cvt.rn.f16x2.f32 t, %2, %1; ex2.approx.f16x2 %0, t; }"
        : "=r"(r) : "f"(lo), "f"(hi));
    return r;
}
__device__ __forceinline__ uint32_t pack_h2(float lo, float hi) {
    uint32_t r;
    asm("cvt.rn.f16x2.f32 %0, %2, %1;" : "=r"(r) : "f"(lo), "f"(hi));
    return r;
}
__device__ __forceinline__ void ldsm4(uint32_t* r, uint32_t a) {
    asm volatile("ldmatrix.sync.aligned.m8n8.x4.shared.b16 {%0,%1,%2,%3}, [%4];"
        : "=r"(r[0]), "=r"(r[1]), "=r"(r[2]), "=r"(r[3]) : "r"(a));
}
__device__ __forceinline__ void ldsm4t(uint32_t* r, uint32_t a) {
    asm volatile("ldmatrix.sync.aligned.m8n8.x4.trans.shared.b16 {%0,%1,%2,%3}, [%4];"
        : "=r"(r[0]), "=r"(r[1]), "=r"(r[2]), "=r"(r[3]) : "r"(a));
}
__device__ __forceinline__ void mma_f16(float* d, const uint32_t* a, const uint32_t* b) {
    asm volatile(
        "mma.sync.aligned.m16n8k16.row.col.f32.f16.f16.f32 "
        "{%0,%1,%2,%3}, {%4,%5,%6,%7}, {%8,%9}, {%0,%1,%2,%3};"
        : "+f"(d[0]), "+f"(d[1]), "+f"(d[2]), "+f"(d[3])
        : "r"(a[0]), "r"(a[1]), "r"(a[2]), "r"(a[3]), "r"(b[0]), "r"(b[1]));
}

// 32x32 warp tile, B stored [n][k] row-major (attnP).
__device__ __forceinline__ void warp_mma_32x32(
    float acc[2][4][4], uint32_t sA, uint32_t sB,
    int wm, int wn, int lane, int k0)
{
    const int arow = lane & 15;
    const int acol = k0 + ((lane >> 4) << 3);
    const int brow = (lane & 7) + ((lane >> 4) << 3);
    const int bcol = k0 + ((lane >> 3) & 1) * 8;

    uint32_t a[2][4], bq[2][4];
#pragma unroll
    for (int mf = 0; mf < 2; mf++)
        ldsm4(a[mf], sA + (uint32_t)(((wm * 32 + mf * 16 + arow) * ST + acol) * 2));
#pragma unroll
    for (int pr = 0; pr < 2; pr++)
        ldsm4(bq[pr], sB + (uint32_t)(((wn * 32 + pr * 16 + brow) * ST + bcol) * 2));
#pragma unroll
    for (int mf = 0; mf < 2; mf++)
#pragma unroll
        for (int nf = 0; nf < 4; nf++)
            mma_f16(acc[mf][nf], a[mf], &bq[nf >> 1][(nf & 1) * 2]);
}

// 64x32 warp tile, B stored [k][n] row-major (ldsm4.trans path; px).
__device__ __forceinline__ void warp_mma_64x32_bt(
    float acc[4][4][4], uint32_t sA, uint32_t sB, uint32_t bstride /*halves*/,
    int wm, int wn, int lane, int k0)
{
    const int arow = lane & 15;
    const int acol = k0 + ((lane >> 4) << 3);
    const int bkrow = k0 + ((lane >> 3) & 1) * 8 + (lane & 7);
    const int bncol = wn * 32 + (lane >> 4) * 8;

    uint32_t a[4][4], bq[2][4];
#pragma unroll
    for (int mf = 0; mf < 4; mf++)
        ldsm4(a[mf], sA + (uint32_t)(((wm * 64 + mf * 16 + arow) * ST + acol) * 2));
#pragma unroll
    for (int pr = 0; pr < 2; pr++)
        ldsm4t(bq[pr], sB + (uint32_t)((bkrow * bstride + bncol + pr * 16) * 2));
#pragma unroll
    for (int mf = 0; mf < 4; mf++)
#pragma unroll
        for (int nf = 0; nf < 4; nf++)
            mma_f16(acc[mf][nf], a[mf], &bq[nf >> 1][(nf & 1) * 2]);
}

#define CP_ASYNC16(saddr, gptr) \
    asm volatile("cp.async.cg.shared.global [%0], [%1], 16;" :: "r"(saddr), "l"(gptr))
#define CP_COMMIT() asm volatile("cp.async.commit_group;" ::: "memory")
#define CP_WAIT1()  asm volatile("cp.async.wait_group 1;" ::: "memory")

#define ATTNP_SMEM ((64 * ST + 3 * ATILE) * 2 + 2048)  // 66560 B -> 3 CTAs/SM
#define PXSE       (128 * ST + 64 * ST2)               // px stage halves
#define PX_SMEM    (3 * PXSE * 2)                      // 107520 B -> 2 CTAs/SM
#define PROJ_SMEM  ((64 * ST + 64 * ST) * 2)           // 18432 B

// ---------------------------------------------------------------------------
// proj: grid (256, 2), 64-row tiles. y=0: Q=(h@WQ+bQ)*QSCALE; y=1: K=X@WK+bK.
// W loaded [k][n]; B frags via ldsm4.trans. K-role writes through X fp16 tiles
// to g_Xh. 8 warps as 4x2, warp tile 16x32.
// ---------------------------------------------------------------------------
__global__ __launch_bounds__(256) void proj_kernel(
    const float* __restrict__ X, const float* __restrict__ h,
    const float* __restrict__ WQ, const float* __restrict__ bQ,
    const float* __restrict__ WK, const float* __restrict__ bK)
{
    extern __shared__ __half psm[];
    __half* sA = psm;                 // [64][ST]   (rows = m, cols = k-chunk)
    __half* sW = psm + 64 * ST;       // [64][ST]   (rows = k-chunk, cols = n)

    const int tid = threadIdx.x;
    const int which = blockIdx.y;
    const float* A    = which ? X  : h;
    const float* W    = which ? WK : WQ;
    const float* bias = which ? bK : bQ;
    const float scale = which ? 1.0f : QSCALE;
    __half* O = which ? g_K : g_Q;

    const int m0 = blockIdx.x * 64;
    const int w = tid >> 5, lane = tid & 31;
    const int ws = w >> 1, wn = w & 1;      // 4 x 2 warps, 16x32 tiles

    float acc[4][4];
#pragma unroll
    for (int nf = 0; nf < 4; nf++)
#pragma unroll
        for (int r = 0; r < 4; r++) acc[nf][r] = 0.0f;

    const uint32_t aA = smem_u32(sA);
    const uint32_t aW = smem_u32(sW);
    const int arow = lane & 15;
    const int asel = (lane >> 4) << 3;
    const int bkrow = ((lane >> 3) & 1) * 8 + (lane & 7);
    const int bncol = wn * 32 + (lane >> 4) * 8;

    for (int kb = 0; kb < DIM; kb += 64) {
        __syncthreads();
        // A tile: 64 rows x 64 cols fp32 -> fp16 (+ write-through for K role)
#pragma unroll
        for (int i = tid; i < 64 * 16; i += 256) {
            int r = i >> 4, c4 = i & 15;
            float4 v = *(const float4*)(A + (long)(m0 + r) * DIM + kb + c4 * 4);
            uint2 pk = make_uint2(pack_h2(v.x, v.y), pack_h2(v.z, v.w));
            *(uint2*)(sA + r * ST + c4 * 4) = pk;
            if (which)
                *(uint2*)(g_Xh + (size_t)(m0 + r) * DIM + kb + c4 * 4) = pk;
        }
        // W chunk: 64 k-rows x 64 n fp32 -> fp16
#pragma unroll
        for (int i = tid; i < 64 * 16; i += 256) {
            int r = i >> 4, c4 = i & 15;
            float4 v = *(const float4*)(W + (long)(kb + r) * DK + c4 * 4);
            *(uint2*)(sW + r * ST + c4 * 4) =
                make_uint2(pack_h2(v.x, v.y), pack_h2(v.z, v.w));
        }
        __syncthreads();

#pragma unroll
        for (int ks = 0; ks < 4; ks++) {
            const int k0 = ks * 16;
            uint32_t a[4], bq[2][4];
            ldsm4(a, aA + (uint32_t)(((ws * 16 + arow) * ST + k0 + asel) * 2));
#pragma unroll
            for (int pr = 0; pr < 2; pr++)
                ldsm4t(bq[pr], aW + (uint32_t)(((k0 + bkrow) * ST + bncol + pr * 16) * 2));
#pragma unroll
            for (int nf = 0; nf < 4; nf++)
                mma_f16(acc[nf], a, &bq[nf >> 1][(nf & 1) * 2]);
        }
    }

    const int g = lane >> 2, tg = lane & 3;
    const int r0 = m0 + ws * 16 + g;
#pragma unroll
    for (int nf = 0; nf < 4; nf++) {
        const int c = wn * 32 + nf * 8 + tg * 2;
        const float b0 = __ldg(bias + c), b1 = __ldg(bias + c + 1);
        *(uint32_t*)(O + (long)r0 * DK + c) =
            pack_h2((acc[nf][0] + b0) * scale, (acc[nf][1] + b1) * scale);
        *(uint32_t*)(O + (long)(r0 + 8) * DK + c) =
            pack_h2((acc[nf][2] + b0) * scale, (acc[nf][3] + b1) * scale);
    }
}

// ---------------------------------------------------------------------------
// attnP: grid (32, 8), 64-q tiles, 3 CTAs/SM.
// S = Q K^T (base-2), P~ = 2^S fp16 unnormalized, store 1/rowsum.
// 8 warps as 2x4, warp tile 32x32, 128 keys/iter, 16 iters, 3-stage ring.
// ---------------------------------------------------------------------------
__device__ __forceinline__ void attnp_issue_k(
    __half* sK, const __half* gK, int jt, int tid)
{
    __half* st = sK + (jt % 3) * ATILE;
    const __half* g = gK + (size_t)jt * 128 * DK;
#pragma unroll
    for (int i = tid; i < 1024; i += 256) {
        int r = i >> 3, c = i & 7;
        CP_ASYNC16(smem_u32(st + r * ST + c * 8), g + r * DK + c * 8);
    }
}

__global__ __launch_bounds__(256, 3) void attnP_kernel()
{
    extern __shared__ char smraw[];
    __half* sQ = (__half*)smraw;                    // [64][ST]
    __half* sK = sQ + 64 * ST;                      // 3 x ATILE
    float*  sL = (float*)(smraw + (64 * ST + 3 * ATILE) * 2);   // [64][4]

    const int tid = threadIdx.x;
    const int w = tid >> 5, lane = tid & 31;
    const int wm = w >> 2, wn = w & 3, g = lane >> 2, tg = lane & 3;
    const int m0 = blockIdx.x * 64, b = blockIdx.y;
    const __half* gQ = g_Q + ((size_t)b * SEQ + m0) * DK;
    const __half* gK = g_K + (size_t)b * SEQ * DK;

#pragma unroll
    for (int i = tid; i < 512; i += 256) {
        int r = i >> 3, c = i & 7;
        *(uint4*)(sQ + r * ST + c * 8) = *(const uint4*)(gQ + r * DK + c * 8);
    }

    const uint32_t aQ = smem_u32(sQ);
    const uint32_t aK0 = smem_u32(sK);

    float lsum[4];
#pragma unroll
    for (int i = 0; i < 4; i++) lsum[i] = 0.0f;

    attnp_issue_k(sK, gK, 0, tid); CP_COMMIT();
    attnp_issue_k(sK, gK, 1, tid); CP_COMMIT();

    __half* Pb = g_P + ((size_t)b * SEQ + m0) * SEQ;

    for (int jt = 0; jt < 16; jt++) {
        CP_WAIT1();
        __syncthreads();
        if (jt + 2 < 16) attnp_issue_k(sK, gK, jt + 2, tid);
        CP_COMMIT();

        float acc[2][4][4];
#pragma unroll
        for (int mf = 0; mf < 2; mf++)
#pragma unroll
            for (int nf = 0; nf < 4; nf++)
#pragma unroll
                for (int r = 0; r < 4; r++) acc[mf][nf][r] = 0.0f;

        uint32_t aK = aK0 + (uint32_t)((jt % 3) * ATILE * 2);
#pragma unroll
        for (int ks = 0; ks < 4; ks++)
            warp_mma_32x32(acc, aQ, aK, wm, wn, lane, ks * 16);

        __half* Pt = Pb + (size_t)jt * 128;
#pragma unroll
        for (int mf = 0; mf < 2; mf++) {
            const int r0 = wm * 32 + mf * 16 + g;
#pragma unroll
            for (int hh = 0; hh < 2; hh++) {
                const int row = r0 + 8 * hh;
                __half2 hs = __floats2half2_rn(0.0f, 0.0f);
#pragma unroll
                for (int nf = 0; nf < 4; nf++) {
                    uint32_t pk = pack_ex2(acc[mf][nf][2 * hh], acc[mf][nf][2 * hh + 1]);
                    *(uint32_t*)(Pt + (size_t)row * SEQ + wn * 32 + nf * 8 + tg * 2) = pk;
                    hs = __hadd2(hs, *(__half2*)&pk);
                }
                float2 f2 = __half22float2(hs);
                lsum[mf * 2 + hh] += f2.x + f2.y;
            }
        }
    }

#pragma unroll
    for (int idx = 0; idx < 4; idx++) {
        lsum[idx] += __shfl_xor_sync(0xFFFFFFFFu, lsum[idx], 1);
        lsum[idx] += __shfl_xor_sync(0xFFFFFFFFu, lsum[idx], 2);
    }
    if (tg == 0) {
#pragma unroll
        for (int idx = 0; idx < 4; idx++) {
            int row = wm * 32 + (idx >> 1) * 16 + g + (idx & 1) * 8;
            sL[row * 4 + wn] = lsum[idx];
        }
    }
    __syncthreads();
    if (tid < 64) {
        float l = sL[tid * 4] + sL[tid * 4 + 1] + sL[tid * 4 + 2] + sL[tid * 4 + 3];
        g_Linv[(size_t)b * SEQ + m0 + tid] = 1.0f / l;
    }
}

// ---------------------------------------------------------------------------
// px: out[128q x 128d] = (P~ @ X) * Linv[row]
// X tiles in natural [k][d] layout (g_Xh); B frags via ldsm4.trans.
// 256 thr, 8 warps 2x4 (64x32 tiles), 3-stage ring, 2 CTAs/SM.
// (At the mma.sync m16n8k16 issue-rate floor — do not touch.)
// ---------------------------------------------------------------------------
__device__ __forceinline__ void px_issue(
    __half* smh, const __half* gP, const __half* gX, int kt, int tid)
{
    __half* st = smh + (kt % 3) * PXSE;
    const long ko = (long)kt * 64;
#pragma unroll
    for (int i = tid; i < 1024; i += 256) {     // P: 128 q-rows x 64 k
        int r = i >> 3, c = i & 7;
        CP_ASYNC16(smem_u32(st + r * ST + c * 8), gP + (long)r * SEQ + ko + c * 8);
    }
    __half* sx = st + 128 * ST;                 // X: 64 k-rows x 128 d
#pragma unroll
    for (int i = tid; i < 1024; i += 256) {
        int r = i >> 4, c = i & 15;
        CP_ASYNC16(smem_u32(sx + r * ST2 + c * 8), gX + (ko + r) * DIM + c * 8);
    }
}

__global__ __launch_bounds__(256, 2) void px_kernel(float* __restrict__ out)
{
    extern __shared__ __half smh[];

    const int tid = threadIdx.x, w = tid >> 5, lane = tid & 31;
    const int wm = w >> 2, wn = w & 3;
    const int m0 = blockIdx.x * 128, n0 = blockIdx.y * 128, b = blockIdx.z;

    const __half* gP = g_P  + ((size_t)b * SEQ + m0) * SEQ;
    const __half* gX = g_Xh + (size_t)b * SEQ * DIM + n0;

    float acc[4][4][4];
#pragma unroll
    for (int mf = 0; mf < 4; mf++)
#pragma unroll
        for (int nf = 0; nf < 4; nf++)
#pragma unroll
            for (int r = 0; r < 4; r++) acc[mf][nf][r] = 0.0f;

    px_issue(smh, gP, gX, 0, tid); CP_COMMIT();
    px_issue(smh, gP, gX, 1, tid); CP_COMMIT();

    const uint32_t base0 = smem_u32(smh);
    for (int kt = 0; kt < SEQ / 64; kt++) {
        CP_WAIT1();
        __syncthreads();
        if (kt + 2 < SEQ / 64) px_issue(smh, gP, gX, kt + 2, tid);
        CP_COMMIT();

        uint32_t aP = base0 + (uint32_t)((kt % 3) * PXSE * 2);
        uint32_t aX = aP + 128 * ST * 2;
#pragma unroll
        for (int ks = 0; ks < 4; ks++)
            warp_mma_64x32_bt(acc, aP, aX, ST2, wm, wn, lane, ks * 16);
    }

    const int g = lane >> 2, tg = lane & 3;
    float* dst = out + ((size_t)b * SEQ + m0) * DIM + n0;
    const float* Li = g_Linv + (size_t)b * SEQ + m0;
#pragma unroll
    for (int mf = 0; mf < 4; mf++) {
        int r0 = wm * 64 + mf * 16 + g;
        float i0 = Li[r0];
        float i1 = Li[r0 + 8];
#pragma unroll
        for (int nf = 0; nf < 4; nf++) {
            int c = wn * 32 + nf * 8 + tg * 2;
            *(float2*)&dst[(size_t)r0 * DIM + c] =
                make_float2(acc[mf][nf][0] * i0, acc[mf][nf][1] * i0);
            *(float2*)&dst[(size_t)(r0 + 8) * DIM + c] =
                make_float2(acc[mf][nf][2] * i1, acc[mf][nf][3] * i1);
        }
    }
}

// ---------------------------------------------------------------------------
// kernel_launch
// ---------------------------------------------------------------------------
extern "C" void kernel_launch(void* const* d_in, const int* in_sizes, int n_in,
                              void* d_out, int out_size)
{
    const float* X  = (const float*)d_in[0];
    const float* h  = (const float*)d_in[1];
    const float* WQ = (const float*)d_in[2];
    const float* bQ = (const float*)d_in[3];
    const float* WK = (const float*)d_in[4];
    const float* bK = (const float*)d_in[5];
    float* out = (float*)d_out;

    static int cfg = 0;
    if (!cfg) {
        cudaFuncSetAttribute(proj_kernel,  cudaFuncAttributeMaxDynamicSharedMemorySize, PROJ_SMEM);
        cudaFuncSetAttribute(attnP_kernel, cudaFuncAttributeMaxDynamicSharedMemorySize, ATTNP_SMEM);
        cudaFuncSetAttribute(px_kernel,    cudaFuncAttributeMaxDynamicSharedMemorySize, PX_SMEM);
        cfg = 1;
    }

    proj_kernel<<<dim3(256, 2), 256, PROJ_SMEM>>>(X, h, WQ, bQ, WK, bK);
    attnP_kernel<<<dim3(32, 8), 256, ATTNP_SMEM>>>();
    px_kernel<<<dim3(SEQ / 128, DIM / 128, BATCH), 256, PX_SMEM>>>(out);
}